// round 14
// baseline (speedup 1.0000x reference)
#include <cuda_runtime.h>
#include <cstdint>

#define D_DIM 256
#define N_MAX 4096
#define M_MAX 16384
#define EPSV 1e-12f

// ---------------------------------------------------------------------------
// Scratch (static device arrays; no allocations allowed).
// ---------------------------------------------------------------------------
__device__ float g_x2[N_MAX];
__device__ float g_y2[M_MAX];
__device__ float g_rowsum[N_MAX];
__device__ __align__(16) uint32_t g_Xh[N_MAX * (D_DIM / 2)];   // bf16x2 packed
__device__ __align__(16) uint32_t g_Yh[M_MAX * (D_DIM / 2)];   // bf16x2 packed

// ---------------------------------------------------------------------------
// PTX helpers (arch-portable: ldmatrix / mma.sync / cp.async)
// ---------------------------------------------------------------------------
__device__ __forceinline__ uint32_t smem_u32(const void* p) {
    uint32_t a;
    asm("{ .reg .u64 t; cvta.to.shared.u64 t, %1; cvt.u32.u64 %0, t; }" : "=r"(a) : "l"(p));
    return a;
}
#define CP_ASYNC16(dst, src) asm volatile("cp.async.cg.shared.global [%0], [%1], 16;" :: "r"(dst), "l"(src) : "memory")
#define CP_COMMIT()          asm volatile("cp.async.commit_group;" ::: "memory")
#define CP_WAIT0()           asm volatile("cp.async.wait_group 0;" ::: "memory")
#define CP_WAIT1()           asm volatile("cp.async.wait_group 1;" ::: "memory")

__device__ __forceinline__ void ldmatrix_x4(uint32_t* r, uint32_t addr) {
    asm volatile("ldmatrix.sync.aligned.m8n8.x4.shared.b16 {%0,%1,%2,%3}, [%4];"
                 : "=r"(r[0]), "=r"(r[1]), "=r"(r[2]), "=r"(r[3]) : "r"(addr));
}
__device__ __forceinline__ void mma_bf16(float* c, const uint32_t* a, const uint32_t* b) {
    asm volatile("mma.sync.aligned.m16n8k16.row.col.f32.bf16.bf16.f32 "
                 "{%0,%1,%2,%3}, {%4,%5,%6,%7}, {%8,%9}, {%0,%1,%2,%3};"
                 : "+f"(c[0]), "+f"(c[1]), "+f"(c[2]), "+f"(c[3])
                 : "r"(a[0]), "r"(a[1]), "r"(a[2]), "r"(a[3]), "r"(b[0]), "r"(b[1]));
}

// ---------------------------------------------------------------------------
// Fused prep: fp32 -> bf16 pack + squared norms + scratch/out zeroing.
// (FROZEN: measured ~8.4us, DRAM-latency pinned.)
// ---------------------------------------------------------------------------
__global__ void prep_kernel(const float* __restrict__ X,
                            const float* __restrict__ Y,
                            float* __restrict__ out, int N, int M) {
    int gtid = blockIdx.x * blockDim.x + threadIdx.x;
    if (gtid < N) g_rowsum[gtid] = 0.0f;
    if (gtid == 0) out[0] = 0.0f;

    int warp = gtid >> 5;                 // handles rows 2*warp, 2*warp+1
    int lane = threadIdx.x & 31;
    int rowp = warp * 2;
    if (rowp >= N + M) return;
    const float4* src; uint4* dst; float* nrm; int row;
    if (rowp < N) { src = (const float4*)X; dst = (uint4*)g_Xh; nrm = g_x2; row = rowp; }
    else          { src = (const float4*)Y; dst = (uint4*)g_Yh; nrm = g_y2; row = rowp - N; }

    float4 a1 = src[(row + 0) * 64 + 2 * lane];
    float4 a2 = src[(row + 0) * 64 + 2 * lane + 1];
    float4 b1 = src[(row + 1) * 64 + 2 * lane];
    float4 b2 = src[(row + 1) * 64 + 2 * lane + 1];

    float sa = a1.x*a1.x + a1.y*a1.y + a1.z*a1.z + a1.w*a1.w
             + a2.x*a2.x + a2.y*a2.y + a2.z*a2.z + a2.w*a2.w;
    float sb = b1.x*b1.x + b1.y*b1.y + b1.z*b1.z + b1.w*b1.w
             + b2.x*b2.x + b2.y*b2.y + b2.z*b2.z + b2.w*b2.w;
#pragma unroll
    for (int o = 16; o; o >>= 1) {
        sa += __shfl_xor_sync(0xffffffffu, sa, o);
        sb += __shfl_xor_sync(0xffffffffu, sb, o);
    }
    if (lane == 0) { nrm[row] = sa; nrm[row + 1] = sb; }

    uint4 q;
    asm("cvt.rn.bf16x2.f32 %0, %1, %2;" : "=r"(q.x) : "f"(a1.y), "f"(a1.x));
    asm("cvt.rn.bf16x2.f32 %0, %1, %2;" : "=r"(q.y) : "f"(a1.w), "f"(a1.z));
    asm("cvt.rn.bf16x2.f32 %0, %1, %2;" : "=r"(q.z) : "f"(a2.y), "f"(a2.x));
    asm("cvt.rn.bf16x2.f32 %0, %1, %2;" : "=r"(q.w) : "f"(a2.w), "f"(a2.z));
    dst[(row + 0) * 32 + lane] = q;
    asm("cvt.rn.bf16x2.f32 %0, %1, %2;" : "=r"(q.x) : "f"(b1.y), "f"(b1.x));
    asm("cvt.rn.bf16x2.f32 %0, %1, %2;" : "=r"(q.y) : "f"(b1.w), "f"(b1.z));
    asm("cvt.rn.bf16x2.f32 %0, %1, %2;" : "=r"(q.z) : "f"(b2.y), "f"(b2.x));
    asm("cvt.rn.bf16x2.f32 %0, %1, %2;" : "=r"(q.w) : "f"(b2.w), "f"(b2.z));
    dst[(row + 1) * 32 + lane] = q;
}

// ---------------------------------------------------------------------------
// Fused distance GEMM via mma.sync bf16 (FROZEN: R12 mainloop, measured 97us,
// ~12.7 cyc/HMMA == legacy-pipe ceiling).
// CTA 128x128, occ 2; K=256 in 4 chunks of 64; 3 smem buffers, wait_group 1.
// Epilogue: direct predicated global atomicAdd.
// ---------------------------------------------------------------------------
#define ROWB   144
#define TILE_B (128 * ROWB)  // 18432 per tile buffer
#define OFF_A  0                      // 3 x TILE_B
#define OFF_B  (3 * TILE_B)           // 3 x TILE_B
#define OFF_X2 (6 * TILE_B)
#define OFF_Y2 (6 * TILE_B + 512)
#define SMEM_DYN (6 * TILE_B + 1024)  // 111616

__global__ __launch_bounds__(256, 2)
void dist_kernel(int N, int M) {
    extern __shared__ __align__(16) char smem[];
    const uint32_t sbase = smem_u32(smem);
    float* x2s = (float*)(smem + OFF_X2);
    float* y2s = (float*)(smem + OFF_Y2);

    const int tid  = threadIdx.x;
    const int wid  = tid >> 5;
    const int lane = tid & 31;
    const int iBase = blockIdx.y * 128;
    const int jBase = blockIdx.x * 128;
    const int iw = (wid >> 2) * 64;
    const int jw = (wid & 3) * 32;

    const uint4* Ag = (const uint4*)g_Xh + (size_t)iBase * 32;
    const uint4* Bg = (const uint4*)g_Yh + (size_t)jBase * 32;

    float acc[4][4][4];
#pragma unroll
    for (int a = 0; a < 4; a++)
#pragma unroll
        for (int b = 0; b < 4; b++)
#pragma unroll
            for (int c = 0; c < 4; c++) acc[a][b][c] = 0.0f;

    if (tid < 128) x2s[tid] = g_x2[iBase + tid];
    else           y2s[tid - 128] = g_y2[jBase + tid - 128];

    auto load_tiles = [&](int buf, int kq) {
#pragma unroll
        for (int t = 0; t < 4; t++) {
            int idx = tid + t * 256;
            int row = idx >> 3, q = idx & 7;
            CP_ASYNC16(sbase + OFF_A + buf * TILE_B + row * ROWB + q * 16,
                       (const void*)(Ag + row * 32 + kq + q));
        }
#pragma unroll
        for (int t = 0; t < 4; t++) {
            int idx = tid + t * 256;
            int row = idx >> 3, q = idx & 7;
            CP_ASYNC16(sbase + OFF_B + buf * TILE_B + row * ROWB + q * 16,
                       (const void*)(Bg + row * 32 + kq + q));
        }
        CP_COMMIT();
    };

    // prologue: 2 chunks in flight
    load_tiles(0, 0);
    load_tiles(1, 8);

    // ldmatrix address components
    const int aRow = lane & 15;
    const int aColSel = (lane >> 4) * 16;
    const int bRow = ((lane & 16) >> 1) + (lane & 7);      // 16-row span
    const int bColSel = ((lane >> 3) & 1) * 16;

#pragma unroll
    for (int kt = 0; kt < 4; kt++) {
        if (kt < 3) CP_WAIT1(); else CP_WAIT0();
        __syncthreads();
        if (kt < 2) load_tiles((kt + 2) % 3, (kt + 2) * 8);

        const int buf = kt % 3;
        const uint32_t sA = sbase + OFF_A + buf * TILE_B;
        const uint32_t sB = sbase + OFF_B + buf * TILE_B;
#pragma unroll
        for (int ks = 0; ks < 4; ks++) {
            uint32_t afr[4][4], bfr[4][2];
#pragma unroll
            for (int mf = 0; mf < 4; mf++)
                ldmatrix_x4(afr[mf], sA + (iw + mf * 16 + aRow) * ROWB
                                        + ks * 32 + aColSel);
#pragma unroll
            for (int np = 0; np < 2; np++) {
                uint32_t r[4];
                ldmatrix_x4(r, sB + (jw + np * 16 + bRow) * ROWB
                                  + ks * 32 + bColSel);
                bfr[2*np][0]   = r[0]; bfr[2*np][1]   = r[1];
                bfr[2*np+1][0] = r[2]; bfr[2*np+1][1] = r[3];
            }
#pragma unroll
            for (int mf = 0; mf < 4; mf++)
#pragma unroll
                for (int nf = 0; nf < 4; nf++)
                    mma_bf16(acc[mf][nf], afr[mf], bfr[nf]);
        }
    }

    // Epilogue: dist + per-row reduction, direct global atomics.
#pragma unroll
    for (int mf = 0; mf < 4; mf++) {
        const int r0 = iw + mf * 16 + (lane >> 2);
        const float x20 = x2s[r0], x21 = x2s[r0 + 8];
        float rs0 = 0.0f, rs1 = 0.0f;
#pragma unroll
        for (int nf = 0; nf < 4; nf++) {
            const int j0 = jw + nf * 8 + (lane & 3) * 2;
            const float y20 = y2s[j0], y21 = y2s[j0 + 1];
            const float* c = acc[mf][nf];
            float d2;
            d2 = fmaxf(fmaf(-2.0f, c[0], x20 + y20), 0.0f) + EPSV; rs0 += d2 * rsqrtf(d2);
            d2 = fmaxf(fmaf(-2.0f, c[1], x20 + y21), 0.0f) + EPSV; rs0 += d2 * rsqrtf(d2);
            d2 = fmaxf(fmaf(-2.0f, c[2], x21 + y20), 0.0f) + EPSV; rs1 += d2 * rsqrtf(d2);
            d2 = fmaxf(fmaf(-2.0f, c[3], x21 + y21), 0.0f) + EPSV; rs1 += d2 * rsqrtf(d2);
        }
        rs0 += __shfl_xor_sync(0xffffffffu, rs0, 1);
        rs0 += __shfl_xor_sync(0xffffffffu, rs0, 2);
        rs1 += __shfl_xor_sync(0xffffffffu, rs1, 1);
        rs1 += __shfl_xor_sync(0xffffffffu, rs1, 2);
        if ((lane & 3) == 0) {
            atomicAdd(&g_rowsum[iBase + r0], rs0);
            atomicAdd(&g_rowsum[iBase + r0 + 8], rs1);
        }
    }
}

// ---------------------------------------------------------------------------
// Loss via |diff| + symmetry: sum_{i,j}|d_i-d_j| = 2 * sum_{i<j}|d_i-d_j|
// (exact identity; |diff| approx error <= N^2*1e-6 ~ 3e-6 rel as before).
// Triangular grid: 136 blocks over 16x16 chunk pairs (ci<=cj), 256x256 each.
// Diagonal blocks sum j>tid only. ~55% of the pair work of the full grid.
// ---------------------------------------------------------------------------
#define NCHUNK 16
#define NTRI   (NCHUNK * (NCHUNK + 1) / 2)   // 136

__global__ void loss_kernel(float* __restrict__ out, int N, float invM) {
    __shared__ __align__(16) float sj[256];
    __shared__ float wsum[8];
    const int tid = threadIdx.x;

    // decode triangular block id -> (ci, cj), ci <= cj
    int b = blockIdx.x;
    int ci = 0;
    while (b >= NCHUNK - ci) { b -= NCHUNK - ci; ci++; }
    const int cj = ci + b;

    const int i  = ci * 256 + tid;
    const int jb = cj * 256;

    sj[tid] = g_rowsum[jb + tid] * invM;
    const float di = g_rowsum[i] * invM;
    __syncthreads();

    float local = 0.0f;
    if (ci == cj) {
        // strictly upper: j > tid within this chunk
        for (int j = tid + 1; j < 256; j++)
            local += fabsf(di - sj[j]);
    } else {
#pragma unroll 8
        for (int j = 0; j < 256; j += 4) {
            float4 v = *(const float4*)&sj[j];
            local += fabsf(di - v.x) + fabsf(di - v.y)
                   + fabsf(di - v.z) + fabsf(di - v.w);
        }
    }
#pragma unroll
    for (int o = 16; o; o >>= 1) local += __shfl_xor_sync(0xffffffffu, local, o);
    int lane = tid & 31, warp = tid >> 5;
    if (lane == 0) wsum[warp] = local;
    __syncthreads();
    if (tid == 0) {
        float s = 0.0f;
#pragma unroll
        for (int w = 0; w < 8; w++) s += wsum[w];
        atomicAdd(out, 2.0f * s);
    }
}

// ---------------------------------------------------------------------------
extern "C" void kernel_launch(void* const* d_in, const int* in_sizes, int n_in,
                              void* d_out, int out_size) {
    const float* X = (const float*)d_in[0];
    const float* Y = (const float*)d_in[1];
    float* out = (float*)d_out;
    const int N = in_sizes[0] / D_DIM;   // 4096
    const int M = in_sizes[1] / D_DIM;   // 16384

    static int attr_done = 0;
    if (!attr_done) {
        cudaFuncSetAttribute(dist_kernel,
                             cudaFuncAttributeMaxDynamicSharedMemorySize, SMEM_DYN);
        attr_done = 1;
    }

    prep_kernel<<<((N + M) * 16 + 255) / 256, 256>>>(X, Y, out, N, M);
    dim3 grid(M / 128, N / 128);
    dist_kernel<<<grid, 256, SMEM_DYN>>>(N, M);
    loss_kernel<<<NTRI, 256>>>(out, N, 1.0f / (float)M);
}

// round 15
// speedup vs baseline: 1.0078x; 1.0078x over previous
#include <cuda_runtime.h>
#include <cstdint>

#define D_DIM 256
#define N_MAX 4096
#define M_MAX 16384
#define EPSV 1e-12f

// ---------------------------------------------------------------------------
// Scratch (static device arrays; no allocations allowed).
// ---------------------------------------------------------------------------
__device__ float g_x2[N_MAX];
__device__ float g_y2[M_MAX];
__device__ float g_rowsum[N_MAX];
__device__ __align__(16) uint32_t g_Xh[N_MAX * (D_DIM / 2)];   // bf16x2 packed
__device__ __align__(16) uint32_t g_Yh[M_MAX * (D_DIM / 2)];   // bf16x2 packed

// ---------------------------------------------------------------------------
// PTX helpers (arch-portable: ldmatrix / mma.sync / cp.async)
// ---------------------------------------------------------------------------
__device__ __forceinline__ uint32_t smem_u32(const void* p) {
    uint32_t a;
    asm("{ .reg .u64 t; cvta.to.shared.u64 t, %1; cvt.u32.u64 %0, t; }" : "=r"(a) : "l"(p));
    return a;
}
#define CP_ASYNC16(dst, src) asm volatile("cp.async.cg.shared.global [%0], [%1], 16;" :: "r"(dst), "l"(src) : "memory")
#define CP_COMMIT()          asm volatile("cp.async.commit_group;" ::: "memory")
#define CP_WAIT0()           asm volatile("cp.async.wait_group 0;" ::: "memory")
#define CP_WAIT1()           asm volatile("cp.async.wait_group 1;" ::: "memory")

__device__ __forceinline__ void ldmatrix_x4(uint32_t* r, uint32_t addr) {
    asm volatile("ldmatrix.sync.aligned.m8n8.x4.shared.b16 {%0,%1,%2,%3}, [%4];"
                 : "=r"(r[0]), "=r"(r[1]), "=r"(r[2]), "=r"(r[3]) : "r"(addr));
}
__device__ __forceinline__ void mma_bf16(float* c, const uint32_t* a, const uint32_t* b) {
    asm volatile("mma.sync.aligned.m16n8k16.row.col.f32.bf16.bf16.f32 "
                 "{%0,%1,%2,%3}, {%4,%5,%6,%7}, {%8,%9}, {%0,%1,%2,%3};"
                 : "+f"(c[0]), "+f"(c[1]), "+f"(c[2]), "+f"(c[3])
                 : "r"(a[0]), "r"(a[1]), "r"(a[2]), "r"(a[3]), "r"(b[0]), "r"(b[1]));
}

// ---------------------------------------------------------------------------
// Fused prep: fp32 -> bf16 pack + squared norms + scratch/out zeroing.
// FOUR rows per warp: 8 independent LDG.128 up front (MLP 8), 4 interleaved
// shuffle trees (4-way ILP on the SHFL chain), 4 contiguous STG.128.
// ---------------------------------------------------------------------------
__global__ void prep_kernel(const float* __restrict__ X,
                            const float* __restrict__ Y,
                            float* __restrict__ out, int N, int M) {
    int gtid = blockIdx.x * blockDim.x + threadIdx.x;
    if (gtid < N) g_rowsum[gtid] = 0.0f;
    if (gtid == 0) out[0] = 0.0f;

    int warp = gtid >> 5;                 // handles rows 4*warp .. 4*warp+3
    int lane = threadIdx.x & 31;
    int rowp = warp * 4;
    if (rowp >= N + M) return;
    const float4* src; uint4* dst; float* nrm; int row;
    if (rowp < N) { src = (const float4*)X; dst = (uint4*)g_Xh; nrm = g_x2; row = rowp; }
    else          { src = (const float4*)Y; dst = (uint4*)g_Yh; nrm = g_y2; row = rowp - N; }

    // 8 independent loads, back-to-back (elements 8*lane..8*lane+7 per row)
    float4 v[4][2];
#pragma unroll
    for (int r = 0; r < 4; r++) {
        v[r][0] = src[(row + r) * 64 + 2 * lane];
        v[r][1] = src[(row + r) * 64 + 2 * lane + 1];
    }

    float s[4];
#pragma unroll
    for (int r = 0; r < 4; r++)
        s[r] = v[r][0].x*v[r][0].x + v[r][0].y*v[r][0].y
             + v[r][0].z*v[r][0].z + v[r][0].w*v[r][0].w
             + v[r][1].x*v[r][1].x + v[r][1].y*v[r][1].y
             + v[r][1].z*v[r][1].z + v[r][1].w*v[r][1].w;
#pragma unroll
    for (int o = 16; o; o >>= 1) {
#pragma unroll
        for (int r = 0; r < 4; r++)
            s[r] += __shfl_xor_sync(0xffffffffu, s[r], o);
    }
    if (lane == 0) {
#pragma unroll
        for (int r = 0; r < 4; r++) nrm[row + r] = s[r];
    }

#pragma unroll
    for (int r = 0; r < 4; r++) {
        uint4 q;
        asm("cvt.rn.bf16x2.f32 %0, %1, %2;" : "=r"(q.x) : "f"(v[r][0].y), "f"(v[r][0].x));
        asm("cvt.rn.bf16x2.f32 %0, %1, %2;" : "=r"(q.y) : "f"(v[r][0].w), "f"(v[r][0].z));
        asm("cvt.rn.bf16x2.f32 %0, %1, %2;" : "=r"(q.z) : "f"(v[r][1].y), "f"(v[r][1].x));
        asm("cvt.rn.bf16x2.f32 %0, %1, %2;" : "=r"(q.w) : "f"(v[r][1].w), "f"(v[r][1].z));
        dst[(row + r) * 32 + lane] = q;
    }
}

// ---------------------------------------------------------------------------
// Fused distance GEMM via mma.sync bf16 (FROZEN: R12 mainloop, measured 97us,
// ~12.7 cyc/HMMA == legacy-pipe ceiling).
// CTA 128x128, occ 2; K=256 in 4 chunks of 64; 3 smem buffers, wait_group 1.
// Epilogue: direct predicated global atomicAdd.
// ---------------------------------------------------------------------------
#define ROWB   144
#define TILE_B (128 * ROWB)  // 18432 per tile buffer
#define OFF_A  0                      // 3 x TILE_B
#define OFF_B  (3 * TILE_B)           // 3 x TILE_B
#define OFF_X2 (6 * TILE_B)
#define OFF_Y2 (6 * TILE_B + 512)
#define SMEM_DYN (6 * TILE_B + 1024)  // 111616

__global__ __launch_bounds__(256, 2)
void dist_kernel(int N, int M) {
    extern __shared__ __align__(16) char smem[];
    const uint32_t sbase = smem_u32(smem);
    float* x2s = (float*)(smem + OFF_X2);
    float* y2s = (float*)(smem + OFF_Y2);

    const int tid  = threadIdx.x;
    const int wid  = tid >> 5;
    const int lane = tid & 31;
    const int iBase = blockIdx.y * 128;
    const int jBase = blockIdx.x * 128;
    const int iw = (wid >> 2) * 64;
    const int jw = (wid & 3) * 32;

    const uint4* Ag = (const uint4*)g_Xh + (size_t)iBase * 32;
    const uint4* Bg = (const uint4*)g_Yh + (size_t)jBase * 32;

    float acc[4][4][4];
#pragma unroll
    for (int a = 0; a < 4; a++)
#pragma unroll
        for (int b = 0; b < 4; b++)
#pragma unroll
            for (int c = 0; c < 4; c++) acc[a][b][c] = 0.0f;

    if (tid < 128) x2s[tid] = g_x2[iBase + tid];
    else           y2s[tid - 128] = g_y2[jBase + tid - 128];

    auto load_tiles = [&](int buf, int kq) {
#pragma unroll
        for (int t = 0; t < 4; t++) {
            int idx = tid + t * 256;
            int row = idx >> 3, q = idx & 7;
            CP_ASYNC16(sbase + OFF_A + buf * TILE_B + row * ROWB + q * 16,
                       (const void*)(Ag + row * 32 + kq + q));
        }
#pragma unroll
        for (int t = 0; t < 4; t++) {
            int idx = tid + t * 256;
            int row = idx >> 3, q = idx & 7;
            CP_ASYNC16(sbase + OFF_B + buf * TILE_B + row * ROWB + q * 16,
                       (const void*)(Bg + row * 32 + kq + q));
        }
        CP_COMMIT();
    };

    // prologue: 2 chunks in flight
    load_tiles(0, 0);
    load_tiles(1, 8);

    // ldmatrix address components
    const int aRow = lane & 15;
    const int aColSel = (lane >> 4) * 16;
    const int bRow = ((lane & 16) >> 1) + (lane & 7);      // 16-row span
    const int bColSel = ((lane >> 3) & 1) * 16;

#pragma unroll
    for (int kt = 0; kt < 4; kt++) {
        if (kt < 3) CP_WAIT1(); else CP_WAIT0();
        __syncthreads();
        if (kt < 2) load_tiles((kt + 2) % 3, (kt + 2) * 8);

        const int buf = kt % 3;
        const uint32_t sA = sbase + OFF_A + buf * TILE_B;
        const uint32_t sB = sbase + OFF_B + buf * TILE_B;
#pragma unroll
        for (int ks = 0; ks < 4; ks++) {
            uint32_t afr[4][4], bfr[4][2];
#pragma unroll
            for (int mf = 0; mf < 4; mf++)
                ldmatrix_x4(afr[mf], sA + (iw + mf * 16 + aRow) * ROWB
                                        + ks * 32 + aColSel);
#pragma unroll
            for (int np = 0; np < 2; np++) {
                uint32_t r[4];
                ldmatrix_x4(r, sB + (jw + np * 16 + bRow) * ROWB
                                  + ks * 32 + bColSel);
                bfr[2*np][0]   = r[0]; bfr[2*np][1]   = r[1];
                bfr[2*np+1][0] = r[2]; bfr[2*np+1][1] = r[3];
            }
#pragma unroll
            for (int mf = 0; mf < 4; mf++)
#pragma unroll
                for (int nf = 0; nf < 4; nf++)
                    mma_bf16(acc[mf][nf], afr[mf], bfr[nf]);
        }
    }

    // Epilogue: dist + per-row reduction, direct global atomics.
#pragma unroll
    for (int mf = 0; mf < 4; mf++) {
        const int r0 = iw + mf * 16 + (lane >> 2);
        const float x20 = x2s[r0], x21 = x2s[r0 + 8];
        float rs0 = 0.0f, rs1 = 0.0f;
#pragma unroll
        for (int nf = 0; nf < 4; nf++) {
            const int j0 = jw + nf * 8 + (lane & 3) * 2;
            const float y20 = y2s[j0], y21 = y2s[j0 + 1];
            const float* c = acc[mf][nf];
            float d2;
            d2 = fmaxf(fmaf(-2.0f, c[0], x20 + y20), 0.0f) + EPSV; rs0 += d2 * rsqrtf(d2);
            d2 = fmaxf(fmaf(-2.0f, c[1], x20 + y21), 0.0f) + EPSV; rs0 += d2 * rsqrtf(d2);
            d2 = fmaxf(fmaf(-2.0f, c[2], x21 + y20), 0.0f) + EPSV; rs1 += d2 * rsqrtf(d2);
            d2 = fmaxf(fmaf(-2.0f, c[3], x21 + y21), 0.0f) + EPSV; rs1 += d2 * rsqrtf(d2);
        }
        rs0 += __shfl_xor_sync(0xffffffffu, rs0, 1);
        rs0 += __shfl_xor_sync(0xffffffffu, rs0, 2);
        rs1 += __shfl_xor_sync(0xffffffffu, rs1, 1);
        rs1 += __shfl_xor_sync(0xffffffffu, rs1, 2);
        if ((lane & 3) == 0) {
            atomicAdd(&g_rowsum[iBase + r0], rs0);
            atomicAdd(&g_rowsum[iBase + r0 + 8], rs1);
        }
    }
}

// ---------------------------------------------------------------------------
// Loss via |diff| + symmetry: sum_{i,j}|d_i-d_j| = 2 * sum_{i<j}|d_i-d_j|
// (exact identity; |diff| approx error <= N^2*1e-6 ~ 3e-6 rel).
// Triangular grid: 136 blocks over 16x16 chunk pairs (ci<=cj), 256x256 each.
// ---------------------------------------------------------------------------
#define NCHUNK 16
#define NTRI   (NCHUNK * (NCHUNK + 1) / 2)   // 136

__global__ void loss_kernel(float* __restrict__ out, int N, float invM) {
    __shared__ __align__(16) float sj[256];
    __shared__ float wsum[8];
    const int tid = threadIdx.x;

    // decode triangular block id -> (ci, cj), ci <= cj
    int b = blockIdx.x;
    int ci = 0;
    while (b >= NCHUNK - ci) { b -= NCHUNK - ci; ci++; }
    const int cj = ci + b;

    const int i  = ci * 256 + tid;
    const int jb = cj * 256;

    sj[tid] = g_rowsum[jb + tid] * invM;
    const float di = g_rowsum[i] * invM;
    __syncthreads();

    float local = 0.0f;
    if (ci == cj) {
        for (int j = tid + 1; j < 256; j++)
            local += fabsf(di - sj[j]);
    } else {
#pragma unroll 8
        for (int j = 0; j < 256; j += 4) {
            float4 v = *(const float4*)&sj[j];
            local += fabsf(di - v.x) + fabsf(di - v.y)
                   + fabsf(di - v.z) + fabsf(di - v.w);
        }
    }
#pragma unroll
    for (int o = 16; o; o >>= 1) local += __shfl_xor_sync(0xffffffffu, local, o);
    int lane = tid & 31, warp = tid >> 5;
    if (lane == 0) wsum[warp] = local;
    __syncthreads();
    if (tid == 0) {
        float s = 0.0f;
#pragma unroll
        for (int w = 0; w < 8; w++) s += wsum[w];
        atomicAdd(out, 2.0f * s);
    }
}

// ---------------------------------------------------------------------------
extern "C" void kernel_launch(void* const* d_in, const int* in_sizes, int n_in,
                              void* d_out, int out_size) {
    const float* X = (const float*)d_in[0];
    const float* Y = (const float*)d_in[1];
    float* out = (float*)d_out;
    const int N = in_sizes[0] / D_DIM;   // 4096
    const int M = in_sizes[1] / D_DIM;   // 16384

    static int attr_done = 0;
    if (!attr_done) {
        cudaFuncSetAttribute(dist_kernel,
                             cudaFuncAttributeMaxDynamicSharedMemorySize, SMEM_DYN);
        attr_done = 1;
    }

    prep_kernel<<<((N + M) * 8 + 255) / 256, 256>>>(X, Y, out, N, M);
    dim3 grid(M / 128, N / 128);
    dist_kernel<<<grid, 256, SMEM_DYN>>>(N, M);
    loss_kernel<<<NTRI, 256>>>(out, N, 1.0f / (float)M);
}